// round 1
// baseline (speedup 1.0000x reference)
#include <cuda_runtime.h>
#include <math.h>

#define BB 8
#define CC 256
#define NN 4096      // H*W
#define GG 32
#define CPG 8        // channels per group
#define EPSV 1e-5f

// ---------------- scratch (device globals; no allocations allowed) ----------
__device__ float g_mean[BB * GG];
__device__ float g_rstd[BB * GG];
__device__ float g_norm[(size_t)BB * CC * NN];           //  32 MB
__device__ float g_key [(size_t)BB * CC * NN];           //  32 MB
__device__ float g_val [(size_t)BB * CC * NN];           //  32 MB
__device__ float g_q   [(size_t)BB * CC * NN];           //  32 MB
__device__ float g_attn[(size_t)BB * NN * NN];           // 512 MB
__device__ float g_ao  [(size_t)BB * CC * NN];           //  32 MB

// ---------------- 1. GroupNorm statistics -----------------------------------
__global__ void gn_stats(const float* __restrict__ x) {
    const int bg = blockIdx.x;                 // b*32 + g
    const float* p = x + (size_t)bg * (CPG * NN);
    const int tid = threadIdx.x;
    float s = 0.f, s2 = 0.f;
    for (int i = tid; i < CPG * NN; i += 256) {
        float v = p[i];
        s += v; s2 += v * v;
    }
    __shared__ float sh[256], sh2[256];
    sh[tid] = s; sh2[tid] = s2;
    __syncthreads();
    for (int o = 128; o > 0; o >>= 1) {
        if (tid < o) { sh[tid] += sh[tid + o]; sh2[tid] += sh2[tid + o]; }
        __syncthreads();
    }
    if (tid == 0) {
        const float inv_n = 1.f / (CPG * NN);
        float m   = sh[0] * inv_n;
        float var = sh2[0] * inv_n - m * m;
        g_mean[bg] = m;
        g_rstd[bg] = rsqrtf(var + EPSV);
    }
}

// ---------------- 2. apply GroupNorm -----------------------------------------
__global__ void gn_apply(const float* __restrict__ x,
                         const float* __restrict__ gamma,
                         const float* __restrict__ beta) {
    size_t idx = (size_t)blockIdx.x * blockDim.x + threadIdx.x;
    if (idx >= (size_t)BB * CC * NN) return;
    int c  = (int)((idx / NN) % CC);
    int bg = (int)(idx / ((size_t)CPG * NN));  // groups are 8 contiguous channels
    float v = (x[idx] - g_mean[bg]) * g_rstd[bg];
    g_norm[idx] = v * gamma[c] + beta[c];
}

// ---------------- 3. Q projection (K = 3) ------------------------------------
__global__ void q_proj(const float* __restrict__ qin,   // [B,3,N]
                       const float* __restrict__ wq) {  // [C,3]
    size_t idx = (size_t)blockIdx.x * blockDim.x + threadIdx.x;
    if (idx >= (size_t)BB * CC * NN) return;
    int n = (int)(idx % NN);
    int c = (int)((idx / NN) % CC);
    int b = (int)(idx / ((size_t)CC * NN));
    const float* qb = qin + (size_t)b * 3 * NN + n;
    g_q[idx] = wq[c * 3 + 0] * qb[0]
             + wq[c * 3 + 1] * qb[NN]
             + wq[c * 3 + 2] * qb[2 * NN];
}

// ---------------- 4. KV GEMM: (512x256) @ (256x4096) per batch ---------------
// key/val split at o = 256
__global__ void __launch_bounds__(256) gemm_kv(const float* __restrict__ wkv) {
    const int b  = blockIdx.z;
    const int m0 = blockIdx.y * 128;     // output row (o)
    const int n0 = blockIdx.x * 128;     // output col (n)
    const float* Bp = g_norm + (size_t)b * CC * NN;

    __shared__ float As[8][128];
    __shared__ float Bs[8][128];

    const int tid = threadIdx.x;
    const int tx = tid & 15, ty = tid >> 4;
    const int arow = tid >> 1, ac4 = (tid & 1) * 4;      // A: [m][k] -> transpose
    const int bk = tid >> 5, bn4 = (tid & 31) * 4;       // B: [k][n] -> direct

    float acc[8][8];
#pragma unroll
    for (int i = 0; i < 8; i++)
#pragma unroll
        for (int j = 0; j < 8; j++) acc[i][j] = 0.f;

    for (int k0 = 0; k0 < CC; k0 += 8) {
        float4 a = *(const float4*)&wkv[(m0 + arow) * CC + k0 + ac4];
        As[ac4 + 0][arow] = a.x; As[ac4 + 1][arow] = a.y;
        As[ac4 + 2][arow] = a.z; As[ac4 + 3][arow] = a.w;
        *(float4*)&Bs[bk][bn4] =
            *(const float4*)&Bp[(size_t)(k0 + bk) * NN + n0 + bn4];
        __syncthreads();
#pragma unroll
        for (int k = 0; k < 8; k++) {
            float4 a0 = *(float4*)&As[k][ty * 8];
            float4 a1 = *(float4*)&As[k][ty * 8 + 4];
            float4 b0 = *(float4*)&Bs[k][tx * 8];
            float4 b1 = *(float4*)&Bs[k][tx * 8 + 4];
            float av[8] = {a0.x, a0.y, a0.z, a0.w, a1.x, a1.y, a1.z, a1.w};
            float bv[8] = {b0.x, b0.y, b0.z, b0.w, b1.x, b1.y, b1.z, b1.w};
#pragma unroll
            for (int i = 0; i < 8; i++)
#pragma unroll
                for (int j = 0; j < 8; j++) acc[i][j] += av[i] * bv[j];
        }
        __syncthreads();
    }
#pragma unroll
    for (int i = 0; i < 8; i++) {
        int m = m0 + ty * 8 + i;
        float* dst = (m < CC) ? (g_key + ((size_t)b * CC + m) * NN)
                              : (g_val + ((size_t)b * CC + (m - CC)) * NN);
#pragma unroll
        for (int j = 0; j < 8; j += 4) {
            float4 v = make_float4(acc[i][j], acc[i][j+1], acc[i][j+2], acc[i][j+3]);
            *(float4*)&dst[n0 + tx * 8 + j] = v;
        }
    }
}

// ---------------- 5. QK^T GEMM: S[i][j] = sum_c q[c][i]*key[c][j] * scale ----
__global__ void __launch_bounds__(256) gemm_qk() {
    const int b  = blockIdx.z;
    const int m0 = blockIdx.y * 128;     // query index
    const int n0 = blockIdx.x * 128;     // key index
    const float* Qp = g_q   + (size_t)b * CC * NN;   // [C][N]
    const float* Kp = g_key + (size_t)b * CC * NN;   // [C][N]

    __shared__ float As[8][128];
    __shared__ float Bs[8][128];

    const int tid = threadIdx.x;
    const int tx = tid & 15, ty = tid >> 4;
    const int lk = tid >> 5, ln4 = (tid & 31) * 4;   // both operands coalesced

    float acc[8][8];
#pragma unroll
    for (int i = 0; i < 8; i++)
#pragma unroll
        for (int j = 0; j < 8; j++) acc[i][j] = 0.f;

    for (int k0 = 0; k0 < CC; k0 += 8) {
        *(float4*)&As[lk][ln4] = *(const float4*)&Qp[(size_t)(k0 + lk) * NN + m0 + ln4];
        *(float4*)&Bs[lk][ln4] = *(const float4*)&Kp[(size_t)(k0 + lk) * NN + n0 + ln4];
        __syncthreads();
#pragma unroll
        for (int k = 0; k < 8; k++) {
            float4 a0 = *(float4*)&As[k][ty * 8];
            float4 a1 = *(float4*)&As[k][ty * 8 + 4];
            float4 b0 = *(float4*)&Bs[k][tx * 8];
            float4 b1 = *(float4*)&Bs[k][tx * 8 + 4];
            float av[8] = {a0.x, a0.y, a0.z, a0.w, a1.x, a1.y, a1.z, a1.w};
            float bv[8] = {b0.x, b0.y, b0.z, b0.w, b1.x, b1.y, b1.z, b1.w};
#pragma unroll
            for (int i = 0; i < 8; i++)
#pragma unroll
                for (int j = 0; j < 8; j++) acc[i][j] += av[i] * bv[j];
        }
        __syncthreads();
    }
    const float scale = 0.0625f;   // 1/sqrt(256)
    float* Sp = g_attn + (size_t)b * NN * NN;
#pragma unroll
    for (int i = 0; i < 8; i++) {
        int m = m0 + ty * 8 + i;
#pragma unroll
        for (int j = 0; j < 8; j += 4) {
            float4 v = make_float4(acc[i][j] * scale, acc[i][j+1] * scale,
                                   acc[i][j+2] * scale, acc[i][j+3] * scale);
            *(float4*)&Sp[(size_t)m * NN + n0 + tx * 8 + j] = v;
        }
    }
}

// ---------------- 6. row softmax (rows of 4096) ------------------------------
__global__ void __launch_bounds__(256) softmax_k() {
    const size_t row = blockIdx.x;            // b*4096 + i, 32768 rows
    float* p = g_attn + row * NN;
    const int tid = threadIdx.x;

    float v[16];
    float mx = -INFINITY;
#pragma unroll
    for (int i = 0; i < 16; i++) {
        v[i] = p[i * 256 + tid];
        mx = fmaxf(mx, v[i]);
    }
    __shared__ float sh[256];
    sh[tid] = mx; __syncthreads();
    for (int o = 128; o > 0; o >>= 1) {
        if (tid < o) sh[tid] = fmaxf(sh[tid], sh[tid + o]);
        __syncthreads();
    }
    mx = sh[0];
    __syncthreads();

    float s = 0.f;
#pragma unroll
    for (int i = 0; i < 16; i++) {
        v[i] = __expf(v[i] - mx);
        s += v[i];
    }
    sh[tid] = s; __syncthreads();
    for (int o = 128; o > 0; o >>= 1) {
        if (tid < o) sh[tid] += sh[tid + o];
        __syncthreads();
    }
    float inv = 1.f / sh[0];
#pragma unroll
    for (int i = 0; i < 16; i++)
        p[i * 256 + tid] = v[i] * inv;
}

// ---------------- 7. PV GEMM: ao[c][n] = sum_j val[c][j] * P[n][j] -----------
__global__ void __launch_bounds__(256) gemm_pv() {
    const int b  = blockIdx.z;
    const int m0 = blockIdx.y * 128;     // channel
    const int n0 = blockIdx.x * 128;     // query index
    const float* Vp = g_val  + (size_t)b * CC * NN;   // [C][j]
    const float* Pp = g_attn + (size_t)b * NN * NN;   // [n][j]

    __shared__ float As[8][128];
    __shared__ float Bs[8][128];

    const int tid = threadIdx.x;
    const int tx = tid & 15, ty = tid >> 4;
    const int row = tid >> 1, c4 = (tid & 1) * 4;   // both transposed loads

    float acc[8][8];
#pragma unroll
    for (int i = 0; i < 8; i++)
#pragma unroll
        for (int j = 0; j < 8; j++) acc[i][j] = 0.f;

    for (int k0 = 0; k0 < NN; k0 += 8) {
        float4 a = *(const float4*)&Vp[(size_t)(m0 + row) * NN + k0 + c4];
        As[c4 + 0][row] = a.x; As[c4 + 1][row] = a.y;
        As[c4 + 2][row] = a.z; As[c4 + 3][row] = a.w;
        float4 pb = *(const float4*)&Pp[(size_t)(n0 + row) * NN + k0 + c4];
        Bs[c4 + 0][row] = pb.x; Bs[c4 + 1][row] = pb.y;
        Bs[c4 + 2][row] = pb.z; Bs[c4 + 3][row] = pb.w;
        __syncthreads();
#pragma unroll
        for (int k = 0; k < 8; k++) {
            float4 a0 = *(float4*)&As[k][ty * 8];
            float4 a1 = *(float4*)&As[k][ty * 8 + 4];
            float4 b0 = *(float4*)&Bs[k][tx * 8];
            float4 b1 = *(float4*)&Bs[k][tx * 8 + 4];
            float av[8] = {a0.x, a0.y, a0.z, a0.w, a1.x, a1.y, a1.z, a1.w};
            float bv[8] = {b0.x, b0.y, b0.z, b0.w, b1.x, b1.y, b1.z, b1.w};
#pragma unroll
            for (int i = 0; i < 8; i++)
#pragma unroll
                for (int j = 0; j < 8; j++) acc[i][j] += av[i] * bv[j];
        }
        __syncthreads();
    }
#pragma unroll
    for (int i = 0; i < 8; i++) {
        int m = m0 + ty * 8 + i;
        float* dst = g_ao + ((size_t)b * CC + m) * NN;
#pragma unroll
        for (int j = 0; j < 8; j += 4) {
            float4 v = make_float4(acc[i][j], acc[i][j+1], acc[i][j+2], acc[i][j+3]);
            *(float4*)&dst[n0 + tx * 8 + j] = v;
        }
    }
}

// ---------------- 8. output GEMM + bias + residual ---------------------------
__global__ void __launch_bounds__(256) gemm_out(const float* __restrict__ wout,
                                                const float* __restrict__ bout,
                                                const float* __restrict__ xin,
                                                float* __restrict__ out) {
    const int b  = blockIdx.z;
    const int m0 = blockIdx.y * 128;     // output channel
    const int n0 = blockIdx.x * 128;     // spatial
    const float* Bp = g_ao + (size_t)b * CC * NN;

    __shared__ float As[8][128];
    __shared__ float Bs[8][128];

    const int tid = threadIdx.x;
    const int tx = tid & 15, ty = tid >> 4;
    const int arow = tid >> 1, ac4 = (tid & 1) * 4;
    const int bk = tid >> 5, bn4 = (tid & 31) * 4;

    float acc[8][8];
#pragma unroll
    for (int i = 0; i < 8; i++)
#pragma unroll
        for (int j = 0; j < 8; j++) acc[i][j] = 0.f;

    for (int k0 = 0; k0 < CC; k0 += 8) {
        float4 a = *(const float4*)&wout[(m0 + arow) * CC + k0 + ac4];
        As[ac4 + 0][arow] = a.x; As[ac4 + 1][arow] = a.y;
        As[ac4 + 2][arow] = a.z; As[ac4 + 3][arow] = a.w;
        *(float4*)&Bs[bk][bn4] =
            *(const float4*)&Bp[(size_t)(k0 + bk) * NN + n0 + bn4];
        __syncthreads();
#pragma unroll
        for (int k = 0; k < 8; k++) {
            float4 a0 = *(float4*)&As[k][ty * 8];
            float4 a1 = *(float4*)&As[k][ty * 8 + 4];
            float4 b0 = *(float4*)&Bs[k][tx * 8];
            float4 b1 = *(float4*)&Bs[k][tx * 8 + 4];
            float av[8] = {a0.x, a0.y, a0.z, a0.w, a1.x, a1.y, a1.z, a1.w};
            float bv[8] = {b0.x, b0.y, b0.z, b0.w, b1.x, b1.y, b1.z, b1.w};
#pragma unroll
            for (int i = 0; i < 8; i++)
#pragma unroll
                for (int j = 0; j < 8; j++) acc[i][j] += av[i] * bv[j];
        }
        __syncthreads();
    }
#pragma unroll
    for (int i = 0; i < 8; i++) {
        int m = m0 + ty * 8 + i;
        float bias = bout[m];
        const float* xr = xin + ((size_t)b * CC + m) * NN;
        float* dst = out + ((size_t)b * CC + m) * NN;
#pragma unroll
        for (int j = 0; j < 8; j += 4) {
            int n = n0 + tx * 8 + j;
            float4 r = *(const float4*)&xr[n];
            float4 v = make_float4(acc[i][j]   + bias + r.x,
                                   acc[i][j+1] + bias + r.y,
                                   acc[i][j+2] + bias + r.z,
                                   acc[i][j+3] + bias + r.w);
            *(float4*)&dst[n] = v;
        }
    }
}

// ---------------- launch ------------------------------------------------------
extern "C" void kernel_launch(void* const* d_in, const int* in_sizes, int n_in,
                              void* d_out, int out_size) {
    const float* input = (const float*)d_in[0];
    const float* quary = (const float*)d_in[1];
    const float* gw    = (const float*)d_in[2];
    const float* gb    = (const float*)d_in[3];
    const float* wq    = (const float*)d_in[4];
    const float* wkv   = (const float*)d_in[5];
    const float* wout  = (const float*)d_in[6];
    const float* bout  = (const float*)d_in[7];
    float* out = (float*)d_out;

    const int total = BB * CC * NN;   // 8388608

    gn_stats<<<BB * GG, 256>>>(input);
    gn_apply<<<(total + 255) / 256, 256>>>(input, gw, gb);
    q_proj  <<<(total + 255) / 256, 256>>>(quary, wq);
    gemm_kv <<<dim3(NN / 128, (2 * CC) / 128, BB), 256>>>(wkv);
    gemm_qk <<<dim3(NN / 128, NN / 128, BB), 256>>>();
    softmax_k<<<BB * NN, 256>>>();
    gemm_pv <<<dim3(NN / 128, CC / 128, BB), 256>>>();
    gemm_out<<<dim3(NN / 128, CC / 128, BB), 256>>>(wout, bout, input, out);
}

// round 2
// speedup vs baseline: 2.2806x; 2.2806x over previous
#include <cuda_runtime.h>
#include <math.h>
#include <stdint.h>

#define BB 8
#define CC 256
#define NN 4096      // H*W
#define GG 32
#define CPG 8        // channels per group
#define EPSV 1e-5f

// ---------------- scratch (device globals; no allocations allowed) ----------
__device__ float g_mean[BB * GG];
__device__ float g_rstd[BB * GG];
__device__ float g_qT  [(size_t)BB * NN * CC];   // Q^T  [b][n][c], pre-scaled
__device__ float g_keyT[(size_t)BB * NN * CC];   // K^T  [b][n][c]
__device__ float g_val [(size_t)BB * CC * NN];   // V    [b][c][n]
__device__ float g_attn[(size_t)BB * NN * NN];   // S/P  [b][m][n]  512 MB
__device__ float g_aoT [(size_t)BB * NN * CC];   // AO^T [b][n][c]

// ---------------- 1. GroupNorm statistics -----------------------------------
__global__ void gn_stats(const float* __restrict__ x) {
    const int bg = blockIdx.x;                 // b*32 + g
    const float* p = x + (size_t)bg * (CPG * NN);
    const int tid = threadIdx.x;
    float s = 0.f, s2 = 0.f;
    for (int i = tid; i < CPG * NN; i += 256) {
        float v = p[i];
        s += v; s2 += v * v;
    }
    __shared__ float sh[256], sh2[256];
    sh[tid] = s; sh2[tid] = s2;
    __syncthreads();
    for (int o = 128; o > 0; o >>= 1) {
        if (tid < o) { sh[tid] += sh[tid + o]; sh2[tid] += sh2[tid + o]; }
        __syncthreads();
    }
    if (tid == 0) {
        const float inv_n = 1.f / (CPG * NN);
        float m   = sh[0] * inv_n;
        float var = sh2[0] * inv_n - m * m;
        g_mean[bg] = m;
        g_rstd[bg] = rsqrtf(var + EPSV);
    }
}

// ---------------- 2. Q projection, transposed + pre-scaled -------------------
__global__ void q_proj_t(const float* __restrict__ qin,   // [B,3,N]
                         const float* __restrict__ wq) {  // [C,3]
    size_t idx = (size_t)blockIdx.x * 256 + threadIdx.x;  // b*N*C + n*C + c
    if (idx >= (size_t)BB * NN * CC) return;
    int c = (int)(idx & (CC - 1));
    int n = (int)((idx >> 8) & (NN - 1));
    int b = (int)(idx >> 20);
    const float* qb = qin + (size_t)b * 3 * NN + n;
    g_qT[idx] = 0.0625f * (wq[c * 3 + 0] * qb[0]
                         + wq[c * 3 + 1] * qb[NN]
                         + wq[c * 3 + 2] * qb[2 * NN]);
}

// ---------------- 3. KV GEMM with fused GroupNorm; K written transposed ------
__global__ void __launch_bounds__(256) gemm_kv(const float* __restrict__ wkv,
                                               const float* __restrict__ xin,
                                               const float* __restrict__ gamma,
                                               const float* __restrict__ beta) {
    const int b  = blockIdx.z;
    const int m0 = blockIdx.y * 128;     // output row (o), 0..511
    const int n0 = blockIdx.x * 128;     // output col (n)

    __shared__ float As[8][128];
    __shared__ float Bs[8][128];

    const int tid = threadIdx.x;
    const int tx = tid & 15, ty = tid >> 4;
    const int arow = tid >> 1, ac4 = (tid & 1) * 4;      // A: [m][k] -> transpose
    const int bk = tid >> 5, bn4 = (tid & 31) * 4;       // B: [k][n] -> direct

    float acc[8][8];
#pragma unroll
    for (int i = 0; i < 8; i++)
#pragma unroll
        for (int j = 0; j < 8; j++) acc[i][j] = 0.f;

    for (int k0 = 0; k0 < CC; k0 += 8) {
        float4 a = *(const float4*)&wkv[(m0 + arow) * CC + k0 + ac4];
        As[ac4 + 0][arow] = a.x; As[ac4 + 1][arow] = a.y;
        As[ac4 + 2][arow] = a.z; As[ac4 + 3][arow] = a.w;
        // fused GroupNorm on the activation tile
        {
            int c  = k0 + bk;
            int bg = b * GG + (c >> 3);
            float sc = g_rstd[bg] * gamma[c];
            float sh = beta[c] - g_mean[bg] * sc;
            float4 x = *(const float4*)&xin[((size_t)b * CC + c) * NN + n0 + bn4];
            Bs[bk][bn4 + 0] = x.x * sc + sh;
            Bs[bk][bn4 + 1] = x.y * sc + sh;
            Bs[bk][bn4 + 2] = x.z * sc + sh;
            Bs[bk][bn4 + 3] = x.w * sc + sh;
        }
        __syncthreads();
#pragma unroll
        for (int k = 0; k < 8; k++) {
            float4 a0 = *(float4*)&As[k][ty * 8];
            float4 a1 = *(float4*)&As[k][ty * 8 + 4];
            float4 b0 = *(float4*)&Bs[k][tx * 8];
            float4 b1 = *(float4*)&Bs[k][tx * 8 + 4];
            float av[8] = {a0.x, a0.y, a0.z, a0.w, a1.x, a1.y, a1.z, a1.w};
            float bv[8] = {b0.x, b0.y, b0.z, b0.w, b1.x, b1.y, b1.z, b1.w};
#pragma unroll
            for (int i = 0; i < 8; i++)
#pragma unroll
                for (int j = 0; j < 8; j++) acc[i][j] += av[i] * bv[j];
        }
        __syncthreads();
    }
    if (m0 < CC) {
        // key half: write transposed  g_keyT[b][n][m]
#pragma unroll
        for (int j = 0; j < 8; j++) {
            int n = n0 + tx * 8 + j;
            float* base = g_keyT + ((size_t)b * NN + n) * CC + m0 + ty * 8;
            *(float4*)base       = make_float4(acc[0][j], acc[1][j], acc[2][j], acc[3][j]);
            *(float4*)(base + 4) = make_float4(acc[4][j], acc[5][j], acc[6][j], acc[7][j]);
        }
    } else {
#pragma unroll
        for (int i = 0; i < 8; i++) {
            int m = m0 - CC + ty * 8 + i;
            float* dst = g_val + ((size_t)b * CC + m) * NN;
#pragma unroll
            for (int j = 0; j < 8; j += 4) {
                *(float4*)&dst[n0 + tx * 8 + j] =
                    make_float4(acc[i][j], acc[i][j+1], acc[i][j+2], acc[i][j+3]);
            }
        }
    }
}

// ---------------- generic TN tf32 tensor-core GEMM ---------------------------
// C[m][n] = sum_k A[m][k] * B[n][k]   (both operands k-contiguous)
// optional: bias[m], residual add, or transposed output Ct[n][m]
__device__ __forceinline__ uint32_t f2tf(float x) {
    uint32_t r; asm("cvt.rna.tf32.f32 %0, %1;" : "=r"(r) : "f"(x)); return r;
}

__global__ void __launch_bounds__(256) gemm_tn_tf32(
    const float* __restrict__ Ag, const float* __restrict__ Bg,
    float* __restrict__ Cg, float* __restrict__ CgT,
    const float* __restrict__ bias, const float* __restrict__ resid,
    int K, int ldc, int ldct,
    size_t sA, size_t sB, size_t sC, size_t sR)
{
    const int b = blockIdx.z;
    const float* A = Ag + (size_t)b * sA;
    const float* B = Bg + (size_t)b * sB;
    const int m0 = blockIdx.y * 128;
    const int n0 = blockIdx.x * 128;

    __shared__ uint32_t As[128 * 20];
    __shared__ uint32_t Bs[128 * 20];

    const int tid  = threadIdx.x;
    const int lane = tid & 31;
    const int warp = tid >> 5;
    const int wm = (warp & 3) * 32;
    const int wn = (warp >> 2) * 64;
    const int g = lane >> 2, t = lane & 3;

    const int lr = tid >> 2;          // 0..63
    const int lk = (tid & 3) * 4;     // 0,4,8,12
    const float* Ap = A + (size_t)(m0 + lr) * K + lk;
    const float* Bp = B + (size_t)(n0 + lr) * K + lk;

    float acc[2][8][4];
#pragma unroll
    for (int mi = 0; mi < 2; mi++)
#pragma unroll
        for (int ni = 0; ni < 8; ni++)
#pragma unroll
            for (int r = 0; r < 4; r++) acc[mi][ni][r] = 0.f;

    float4 ra0, ra1, rb0, rb1;

#define LOAD_TILE(koff)                                                     \
    do {                                                                    \
        ra0 = *(const float4*)(Ap + (koff));                                \
        ra1 = *(const float4*)(Ap + (size_t)64 * K + (koff));               \
        rb0 = *(const float4*)(Bp + (koff));                                \
        rb1 = *(const float4*)(Bp + (size_t)64 * K + (koff));               \
    } while (0)

#define STORE_TILE()                                                        \
    do {                                                                    \
        *(uint4*)&As[lr * 20 + lk] =                                        \
            make_uint4(f2tf(ra0.x), f2tf(ra0.y), f2tf(ra0.z), f2tf(ra0.w)); \
        *(uint4*)&As[(lr + 64) * 20 + lk] =                                 \
            make_uint4(f2tf(ra1.x), f2tf(ra1.y), f2tf(ra1.z), f2tf(ra1.w)); \
        *(uint4*)&Bs[lr * 20 + lk] =                                        \
            make_uint4(f2tf(rb0.x), f2tf(rb0.y), f2tf(rb0.z), f2tf(rb0.w)); \
        *(uint4*)&Bs[(lr + 64) * 20 + lk] =                                 \
            make_uint4(f2tf(rb1.x), f2tf(rb1.y), f2tf(rb1.z), f2tf(rb1.w)); \
    } while (0)

    LOAD_TILE(0);
    STORE_TILE();
    __syncthreads();

    const int iters = K >> 4;
    for (int it = 0; it < iters; ++it) {
        const bool more = (it + 1 < iters);
        if (more) LOAD_TILE((it + 1) * 16);

#pragma unroll
        for (int kk = 0; kk < 16; kk += 8) {
            uint32_t af[2][4], bf[8][2];
#pragma unroll
            for (int mi = 0; mi < 2; mi++) {
                int r0 = (wm + mi * 16 + g) * 20 + kk + t;
                af[mi][0] = As[r0];
                af[mi][1] = As[r0 + 8 * 20];
                af[mi][2] = As[r0 + 4];
                af[mi][3] = As[r0 + 8 * 20 + 4];
            }
#pragma unroll
            for (int ni = 0; ni < 8; ni++) {
                int r0 = (wn + ni * 8 + g) * 20 + kk + t;
                bf[ni][0] = Bs[r0];
                bf[ni][1] = Bs[r0 + 4];
            }
#pragma unroll
            for (int mi = 0; mi < 2; mi++)
#pragma unroll
                for (int ni = 0; ni < 8; ni++) {
                    float* d = acc[mi][ni];
                    asm volatile(
                        "mma.sync.aligned.m16n8k8.row.col.f32.tf32.tf32.f32 "
                        "{%0,%1,%2,%3}, {%4,%5,%6,%7}, {%8,%9}, {%0,%1,%2,%3};"
                        : "+f"(d[0]), "+f"(d[1]), "+f"(d[2]), "+f"(d[3])
                        : "r"(af[mi][0]), "r"(af[mi][1]), "r"(af[mi][2]), "r"(af[mi][3]),
                          "r"(bf[ni][0]), "r"(bf[ni][1]));
                }
        }
        __syncthreads();
        if (more) {
            STORE_TILE();
            __syncthreads();
        }
    }

    // epilogue
    if (Cg) {
        float* Cb = Cg + (size_t)b * sC;
#pragma unroll
        for (int mi = 0; mi < 2; mi++)
#pragma unroll
            for (int ni = 0; ni < 8; ni++) {
                int row = m0 + wm + mi * 16 + g;
                int col = n0 + wn + ni * 8 + t * 2;
                float* d = acc[mi][ni];
                float2 v0 = make_float2(d[0], d[1]);
                float2 v1 = make_float2(d[2], d[3]);
                if (bias) {
                    float bb0 = bias[row], bb1 = bias[row + 8];
                    v0.x += bb0; v0.y += bb0;
                    v1.x += bb1; v1.y += bb1;
                }
                if (resid) {
                    const float* R = resid + (size_t)b * sR;
                    float2 r0 = *(const float2*)&R[(size_t)row * ldc + col];
                    float2 r1 = *(const float2*)&R[(size_t)(row + 8) * ldc + col];
                    v0.x += r0.x; v0.y += r0.y;
                    v1.x += r1.x; v1.y += r1.y;
                }
                *(float2*)&Cb[(size_t)row * ldc + col]       = v0;
                *(float2*)&Cb[(size_t)(row + 8) * ldc + col] = v1;
            }
    } else {
        float* Ct = CgT + (size_t)b * sC;
#pragma unroll
        for (int mi = 0; mi < 2; mi++)
#pragma unroll
            for (int ni = 0; ni < 8; ni++) {
                int row = m0 + wm + mi * 16 + g;
                int col = n0 + wn + ni * 8 + t * 2;
                float* d = acc[mi][ni];
                Ct[(size_t)col * ldct + row]           = d[0];
                Ct[(size_t)(col + 1) * ldct + row]     = d[1];
                Ct[(size_t)col * ldct + row + 8]       = d[2];
                Ct[(size_t)(col + 1) * ldct + row + 8] = d[3];
            }
    }
#undef LOAD_TILE
#undef STORE_TILE
}

// ---------------- row softmax (rows of 4096) ---------------------------------
__global__ void __launch_bounds__(256) softmax_k() {
    const size_t row = blockIdx.x;            // b*4096 + i, 32768 rows
    float* p = g_attn + row * NN;
    const int tid = threadIdx.x;

    float v[16];
    float mx = -INFINITY;
#pragma unroll
    for (int i = 0; i < 16; i++) {
        v[i] = p[i * 256 + tid];
        mx = fmaxf(mx, v[i]);
    }
    __shared__ float sh[256];
    sh[tid] = mx; __syncthreads();
    for (int o = 128; o > 0; o >>= 1) {
        if (tid < o) sh[tid] = fmaxf(sh[tid], sh[tid + o]);
        __syncthreads();
    }
    mx = sh[0];
    __syncthreads();

    float s = 0.f;
#pragma unroll
    for (int i = 0; i < 16; i++) {
        v[i] = __expf(v[i] - mx);
        s += v[i];
    }
    sh[tid] = s; __syncthreads();
    for (int o = 128; o > 0; o >>= 1) {
        if (tid < o) sh[tid] += sh[tid + o];
        __syncthreads();
    }
    float inv = 1.f / sh[0];
#pragma unroll
    for (int i = 0; i < 16; i++)
        p[i * 256 + tid] = v[i] * inv;
}

// ---------------- launch ------------------------------------------------------
extern "C" void kernel_launch(void* const* d_in, const int* in_sizes, int n_in,
                              void* d_out, int out_size) {
    const float* input = (const float*)d_in[0];
    const float* quary = (const float*)d_in[1];
    const float* gw    = (const float*)d_in[2];
    const float* gb    = (const float*)d_in[3];
    const float* wq    = (const float*)d_in[4];
    const float* wkv   = (const float*)d_in[5];
    const float* wout  = (const float*)d_in[6];
    const float* bout  = (const float*)d_in[7];
    float* out = (float*)d_out;

    float *p_qT, *p_keyT, *p_val, *p_attn, *p_aoT;
    cudaGetSymbolAddress((void**)&p_qT,   g_qT);
    cudaGetSymbolAddress((void**)&p_keyT, g_keyT);
    cudaGetSymbolAddress((void**)&p_val,  g_val);
    cudaGetSymbolAddress((void**)&p_attn, g_attn);
    cudaGetSymbolAddress((void**)&p_aoT,  g_aoT);

    const size_t sCN = (size_t)CC * NN;   // 1M
    const size_t sNC = (size_t)NN * CC;   // 1M
    const size_t sNNb = (size_t)NN * NN;  // 16M

    gn_stats<<<BB * GG, 256>>>(input);
    q_proj_t<<<(int)(((size_t)BB * NN * CC + 255) / 256), 256>>>(quary, wq);
    gemm_kv<<<dim3(NN / 128, (2 * CC) / 128, BB), 256>>>(wkv, input, gw, gb);

    // S = Q^T K   (scale pre-folded into Q)
    gemm_tn_tf32<<<dim3(NN / 128, NN / 128, BB), 256>>>(
        p_qT, p_keyT, p_attn, nullptr, nullptr, nullptr,
        CC, NN, 0, sNC, sNC, sNNb, 0);

    softmax_k<<<BB * NN, 256>>>();

    // AO^T = (P V^T)^T : A = V [c][j], B = P [n][j] -> Ct[n][c]
    gemm_tn_tf32<<<dim3(NN / 128, CC / 128, BB), 256>>>(
        p_val, p_attn, nullptr, p_aoT, nullptr, nullptr,
        NN, NN, CC, sCN, sNNb, sNC, 0);

    // out = W_out AO + b + input : A = wout [c][k], B = AO^T [n][k]
    gemm_tn_tf32<<<dim3(NN / 128, CC / 128, BB), 256>>>(
        wout, p_aoT, out, nullptr, bout, input,
        CC, NN, 0, 0, sNC, sCN, sCN);
}

// round 3
// speedup vs baseline: 2.8767x; 1.2614x over previous
#include <cuda_runtime.h>
#include <math.h>
#include <stdint.h>

#define BB 8
#define CC 256
#define NN 4096      // H*W
#define GG 32
#define CPG 8
#define EPSV 1e-5f

// GEMM tiling
#define BM 128
#define BN 256
#define BKK 16
#define PAD 20                       // smem row stride in words (16B aligned)
#define STAGE_W ((BM + BN) * PAD)    // 7680 words per stage
#define SMEM_BYTES (2 * STAGE_W * 4) // 61440

// ---------------- scratch (device globals) -----------------------------------
__device__ float g_mean[BB * GG];
__device__ float g_rstd[BB * GG];
__device__ float g_qT   [(size_t)BB * NN * CC];   // Q^T  [b][n][c], scaled, tf32-rounded
__device__ float g_normT[(size_t)BB * NN * CC];   // GN(x)^T [b][n][c], rounded
__device__ float g_keyT [(size_t)BB * NN * CC];   // K^T  [b][n][c], rounded
__device__ float g_val  [(size_t)BB * CC * NN];   // V    [b][c][n], rounded
__device__ float g_attn [(size_t)BB * NN * NN];   // S/P  [b][m][n]
__device__ float g_aoT  [(size_t)BB * NN * CC];   // AO^T [b][n][c], rounded
__device__ float g_wkv_r[2 * CC * CC];
__device__ float g_wout_r[CC * CC];

__device__ __forceinline__ float rtf(float x) {
    uint32_t r; asm("cvt.rna.tf32.f32 %0, %1;" : "=r"(r) : "f"(x));
    return __uint_as_float(r);
}

// ---------------- 1. GroupNorm statistics ------------------------------------
__global__ void gn_stats(const float* __restrict__ x) {
    const int bg = blockIdx.x;
    const float* p = x + (size_t)bg * (CPG * NN);
    const int tid = threadIdx.x;
    float s = 0.f, s2 = 0.f;
    for (int i = tid; i < CPG * NN; i += 256) {
        float v = p[i];
        s += v; s2 += v * v;
    }
    __shared__ float sh[256], sh2[256];
    sh[tid] = s; sh2[tid] = s2;
    __syncthreads();
    for (int o = 128; o > 0; o >>= 1) {
        if (tid < o) { sh[tid] += sh[tid + o]; sh2[tid] += sh2[tid + o]; }
        __syncthreads();
    }
    if (tid == 0) {
        const float inv_n = 1.f / (CPG * NN);
        float m   = sh[0] * inv_n;
        float var = sh2[0] * inv_n - m * m;
        g_mean[bg] = m;
        g_rstd[bg] = rsqrtf(var + EPSV);
    }
}

// ---------------- 2. weight rounding to tf32 ---------------------------------
__global__ void round_w(const float* __restrict__ wkv,
                        const float* __restrict__ wout) {
    int i = blockIdx.x * 256 + threadIdx.x;
    if (i < 2 * CC * CC) g_wkv_r[i] = rtf(wkv[i]);
    if (i < CC * CC)     g_wout_r[i] = rtf(wout[i]);
}

// ---------------- 3. Q projection, transposed + scaled + rounded -------------
__global__ void q_proj_t(const float* __restrict__ qin,   // [B,3,N]
                         const float* __restrict__ wq) {  // [C,3]
    size_t idx = (size_t)blockIdx.x * 256 + threadIdx.x;
    if (idx >= (size_t)BB * NN * CC) return;
    int c = (int)(idx & (CC - 1));
    int n = (int)((idx >> 8) & (NN - 1));
    int b = (int)(idx >> 20);
    const float* qb = qin + (size_t)b * 3 * NN + n;
    g_qT[idx] = rtf(0.0625f * (wq[c * 3 + 0] * qb[0]
                             + wq[c * 3 + 1] * qb[NN]
                             + wq[c * 3 + 2] * qb[2 * NN]));
}

// ---------------- 4. GroupNorm apply + transpose (normT) ---------------------
__global__ void __launch_bounds__(256) norm_t(const float* __restrict__ x,
                                              const float* __restrict__ gamma,
                                              const float* __restrict__ beta) {
    __shared__ float t[32][33];
    const int b  = blockIdx.z;
    const int n0 = blockIdx.x * 32, c0 = blockIdx.y * 32;
    const int tx = threadIdx.x, ty = threadIdx.y;
#pragma unroll
    for (int i = 0; i < 4; i++) {
        int c  = c0 + ty + i * 8;
        int bg = b * GG + (c >> 3);
        float sc = g_rstd[bg] * gamma[c];
        float sh = beta[c] - g_mean[bg] * sc;
        float v = x[((size_t)b * CC + c) * NN + n0 + tx];
        t[ty + i * 8][tx] = rtf(v * sc + sh);
    }
    __syncthreads();
#pragma unroll
    for (int i = 0; i < 4; i++) {
        int n = n0 + ty + i * 8;
        g_normT[((size_t)b * NN + n) * CC + c0 + tx] = t[tx][ty + i * 8];
    }
}

// ---------------- generic TN tf32 tensor-core GEMM (cp.async pipelined) ------
// C[m][n] = sum_k A[m][k] * B[n][k]; operands pre-rounded to tf32.
// mode 0: write C [m][n] (ldc), optional bias[m], resid, rnd
// mode 2: KV split — rows < CC -> Ct[n][m] (keyT, ldct), rows >= CC -> Cg val
#define CP16(d, s) asm volatile("cp.async.cg.shared.global [%0], [%1], 16;" :: "r"(d), "l"(s))

__global__ void __launch_bounds__(256) gemm_tn_tf32(
    const float* __restrict__ Ag, const float* __restrict__ Bg,
    float* __restrict__ Cg, float* __restrict__ Ct,
    const float* __restrict__ bias, const float* __restrict__ resid,
    int K, int ldc, int ldct, int mode, int rnd,
    size_t sA, size_t sB, size_t sC, size_t sCt, size_t sR)
{
    extern __shared__ uint32_t sm[];
    const int b = blockIdx.z;
    const float* A = Ag + (size_t)b * sA;
    const float* B = Bg + (size_t)b * sB;
    const int m0 = blockIdx.y * BM;
    const int n0 = blockIdx.x * BN;

    const int tid  = threadIdx.x;
    const int lane = tid & 31;
    const int warp = tid >> 5;
    const int wm = (warp & 1) * 64;
    const int wn = (warp >> 1) * 64;
    const int g = lane >> 2, t = lane & 3;

    // cp.async thread mapping: 4 threads per row, 16B each
    const int r4 = tid >> 2;           // 0..63
    const int k4 = (tid & 3) * 4;      // 0,4,8,12 (floats)
    const float* Ap = A + (size_t)(m0 + r4) * K + k4;
    const float* Bp = B + (size_t)(n0 + r4) * K + k4;
    const uint32_t sbase = (uint32_t)__cvta_generic_to_shared(sm);

#define ISSUE(s, ko)                                                         \
    do {                                                                     \
        uint32_t as_ = sbase + (uint32_t)(s) * (STAGE_W * 4);                \
        uint32_t bs_ = as_ + BM * PAD * 4;                                   \
        const float* ap_ = Ap + (ko);                                        \
        const float* bp_ = Bp + (ko);                                        \
        CP16(as_ + (r4 * PAD + k4) * 4,         ap_);                        \
        CP16(as_ + ((r4 + 64) * PAD + k4) * 4,  ap_ + (size_t)64 * K);       \
        CP16(bs_ + (r4 * PAD + k4) * 4,         bp_);                        \
        CP16(bs_ + ((r4 + 64) * PAD + k4) * 4,  bp_ + (size_t)64 * K);       \
        CP16(bs_ + ((r4 + 128) * PAD + k4) * 4, bp_ + (size_t)128 * K);      \
        CP16(bs_ + ((r4 + 192) * PAD + k4) * 4, bp_ + (size_t)192 * K);      \
        asm volatile("cp.async.commit_group;");                              \
    } while (0)

    float acc[4][8][4];
#pragma unroll
    for (int mi = 0; mi < 4; mi++)
#pragma unroll
        for (int ni = 0; ni < 8; ni++)
#pragma unroll
            for (int r = 0; r < 4; r++) acc[mi][ni][r] = 0.f;

    const int iters = K >> 4;          // K multiple of 16, iters >= 16 here
    ISSUE(0, 0);
    ISSUE(1, 16);
    asm volatile("cp.async.wait_group 1;");
    __syncthreads();

    for (int it = 0; it < iters; ++it) {
        const uint32_t* As = sm + (it & 1) * STAGE_W;
        const uint32_t* Bs = As + BM * PAD;

#pragma unroll
        for (int kk = 0; kk < 16; kk += 8) {
            uint32_t af[4][4], bf[8][2];
#pragma unroll
            for (int mi = 0; mi < 4; mi++) {
                const uint32_t* p = As + (wm + mi * 16 + g) * PAD + kk + t;
                af[mi][0] = p[0];
                af[mi][1] = p[8 * PAD];
                af[mi][2] = p[4];
                af[mi][3] = p[8 * PAD + 4];
            }
#pragma unroll
            for (int ni = 0; ni < 8; ni++) {
                const uint32_t* p = Bs + (wn + ni * 8 + g) * PAD + kk + t;
                bf[ni][0] = p[0];
                bf[ni][1] = p[4];
            }
#pragma unroll
            for (int mi = 0; mi < 4; mi++)
#pragma unroll
                for (int ni = 0; ni < 8; ni++) {
                    float* d = acc[mi][ni];
                    asm volatile(
                        "mma.sync.aligned.m16n8k8.row.col.f32.tf32.tf32.f32 "
                        "{%0,%1,%2,%3}, {%4,%5,%6,%7}, {%8,%9}, {%0,%1,%2,%3};"
                        : "+f"(d[0]), "+f"(d[1]), "+f"(d[2]), "+f"(d[3])
                        : "r"(af[mi][0]), "r"(af[mi][1]), "r"(af[mi][2]), "r"(af[mi][3]),
                          "r"(bf[ni][0]), "r"(bf[ni][1]));
                }
        }
        __syncthreads();
        if (it + 2 < iters) {
            ISSUE(it & 1, (size_t)(it + 2) * 16);
            asm volatile("cp.async.wait_group 1;");
        } else {
            asm volatile("cp.async.wait_group 0;");
        }
        __syncthreads();
    }

    // ---------------- epilogue ----------------
    if (mode == 0) {
        float* Cb = Cg + (size_t)b * sC;
#pragma unroll
        for (int mi = 0; mi < 4; mi++)
#pragma unroll
            for (int ni = 0; ni < 8; ni++) {
                int row = m0 + wm + mi * 16 + g;
                int col = n0 + wn + ni * 8 + t * 2;
                float* d = acc[mi][ni];
                float2 v0 = make_float2(d[0], d[1]);
                float2 v1 = make_float2(d[2], d[3]);
                if (bias) {
                    float b0 = bias[row], b1 = bias[row + 8];
                    v0.x += b0; v0.y += b0;
                    v1.x += b1; v1.y += b1;
                }
                if (resid) {
                    const float* R = resid + (size_t)b * sR;
                    float2 r0 = *(const float2*)&R[(size_t)row * ldc + col];
                    float2 r1 = *(const float2*)&R[(size_t)(row + 8) * ldc + col];
                    v0.x += r0.x; v0.y += r0.y;
                    v1.x += r1.x; v1.y += r1.y;
                }
                if (rnd) {
                    v0.x = rtf(v0.x); v0.y = rtf(v0.y);
                    v1.x = rtf(v1.x); v1.y = rtf(v1.y);
                }
                *(float2*)&Cb[(size_t)row * ldc + col]       = v0;
                *(float2*)&Cb[(size_t)(row + 8) * ldc + col] = v1;
            }
    } else {
        // KV split epilogue
        float* Tb = Ct + (size_t)b * sCt;     // keyT [n][c], ldct
        float* Vb = Cg + (size_t)b * sC;      // val  [c][n], ldc
#pragma unroll
        for (int mi = 0; mi < 4; mi++)
#pragma unroll
            for (int ni = 0; ni < 8; ni++) {
                int row = m0 + wm + mi * 16 + g;
                int col = n0 + wn + ni * 8 + t * 2;
                float* d = acc[mi][ni];
                if (row < CC) {
                    Tb[(size_t)col * ldct + row]           = rtf(d[0]);
                    Tb[(size_t)(col + 1) * ldct + row]     = rtf(d[1]);
                    Tb[(size_t)col * ldct + row + 8]       = rtf(d[2]);
                    Tb[(size_t)(col + 1) * ldct + row + 8] = rtf(d[3]);
                } else {
                    *(float2*)&Vb[(size_t)(row - CC) * ldc + col] =
                        make_float2(rtf(d[0]), rtf(d[1]));
                    *(float2*)&Vb[(size_t)(row - CC + 8) * ldc + col] =
                        make_float2(rtf(d[2]), rtf(d[3]));
                }
            }
    }
#undef ISSUE
}

// ---------------- row softmax (rows of 4096, float4) -------------------------
__global__ void __launch_bounds__(256) softmax_k() {
    const size_t row = blockIdx.x;
    float4* p = (float4*)(g_attn + row * NN);
    const int tid = threadIdx.x;

    float4 v[4];
    float mx = -INFINITY;
#pragma unroll
    for (int i = 0; i < 4; i++) {
        v[i] = p[tid + i * 256];
        mx = fmaxf(mx, fmaxf(fmaxf(v[i].x, v[i].y), fmaxf(v[i].z, v[i].w)));
    }
    __shared__ float sh[256];
    sh[tid] = mx; __syncthreads();
    for (int o = 128; o > 0; o >>= 1) {
        if (tid < o) sh[tid] = fmaxf(sh[tid], sh[tid + o]);
        __syncthreads();
    }
    mx = sh[0];
    __syncthreads();

    float s = 0.f;
#pragma unroll
    for (int i = 0; i < 4; i++) {
        v[i].x = __expf(v[i].x - mx); v[i].y = __expf(v[i].y - mx);
        v[i].z = __expf(v[i].z - mx); v[i].w = __expf(v[i].w - mx);
        s += v[i].x + v[i].y + v[i].z + v[i].w;
    }
    sh[tid] = s; __syncthreads();
    for (int o = 128; o > 0; o >>= 1) {
        if (tid < o) sh[tid] += sh[tid + o];
        __syncthreads();
    }
    float inv = 1.f / sh[0];
#pragma unroll
    for (int i = 0; i < 4; i++) {
        p[tid + i * 256] = make_float4(rtf(v[i].x * inv), rtf(v[i].y * inv),
                                       rtf(v[i].z * inv), rtf(v[i].w * inv));
    }
}

// ---------------- launch ------------------------------------------------------
extern "C" void kernel_launch(void* const* d_in, const int* in_sizes, int n_in,
                              void* d_out, int out_size) {
    const float* input = (const float*)d_in[0];
    const float* quary = (const float*)d_in[1];
    const float* gw    = (const float*)d_in[2];
    const float* gb    = (const float*)d_in[3];
    const float* wq    = (const float*)d_in[4];
    const float* wkv   = (const float*)d_in[5];
    const float* wout  = (const float*)d_in[6];
    const float* bout  = (const float*)d_in[7];
    float* out = (float*)d_out;

    static int smem_set = 0;
    if (!smem_set) {
        cudaFuncSetAttribute(gemm_tn_tf32,
                             cudaFuncAttributeMaxDynamicSharedMemorySize, SMEM_BYTES);
        smem_set = 1;
    }

    float *p_qT, *p_normT, *p_keyT, *p_val, *p_attn, *p_aoT, *p_wkv, *p_wout;
    cudaGetSymbolAddress((void**)&p_qT,    g_qT);
    cudaGetSymbolAddress((void**)&p_normT, g_normT);
    cudaGetSymbolAddress((void**)&p_keyT,  g_keyT);
    cudaGetSymbolAddress((void**)&p_val,   g_val);
    cudaGetSymbolAddress((void**)&p_attn,  g_attn);
    cudaGetSymbolAddress((void**)&p_aoT,   g_aoT);
    cudaGetSymbolAddress((void**)&p_wkv,   g_wkv_r);
    cudaGetSymbolAddress((void**)&p_wout,  g_wout_r);

    const size_t sCN  = (size_t)CC * NN;
    const size_t sNC  = (size_t)NN * CC;
    const size_t sNNb = (size_t)NN * NN;

    gn_stats<<<BB * GG, 256>>>(input);
    round_w<<<512, 256>>>(wkv, wout);
    q_proj_t<<<(int)(((size_t)BB * NN * CC + 255) / 256), 256>>>(quary, wq);
    norm_t<<<dim3(NN / 32, CC / 32, BB), dim3(32, 8)>>>(input, gw, gb);

    // KV: A = wkv_r [512][256], B = normT [n][256] -> keyT + val (split)
    gemm_tn_tf32<<<dim3(NN / BN, 512 / BM, BB), 256, SMEM_BYTES>>>(
        p_wkv, p_normT, p_val, p_keyT, nullptr, nullptr,
        CC, NN, CC, 2, 1, 0, sNC, sCN, sNC, 0);

    // S = Q^T K : A = qT, B = keyT -> attn [m][n]
    gemm_tn_tf32<<<dim3(NN / BN, NN / BM, BB), 256, SMEM_BYTES>>>(
        p_qT, p_keyT, p_attn, nullptr, nullptr, nullptr,
        CC, NN, 0, 0, 0, sNC, sNC, sNNb, 0, 0);

    softmax_k<<<BB * NN, 256>>>();

    // AO^T: A = P [q][j], B = val [c][j] -> aoT [q][c] (rounded)
    gemm_tn_tf32<<<dim3(CC / BN, NN / BM, BB), 256, SMEM_BYTES>>>(
        p_attn, p_val, p_aoT, nullptr, nullptr, nullptr,
        NN, CC, 0, 0, 1, sNNb, sCN, sNC, 0, 0);

    // out = W_out AO + b + input : A = wout_r, B = aoT
    gemm_tn_tf32<<<dim3(NN / BN, CC / BM, BB), 256, SMEM_BYTES>>>(
        p_wout, p_aoT, out, nullptr, bout, input,
        CC, NN, 0, 0, 0, 0, sNC, sCN, 0, sCN);
}

// round 4
// speedup vs baseline: 5.0128x; 1.7426x over previous
#include <cuda_runtime.h>
#include <cuda_fp16.h>
#include <math.h>
#include <stdint.h>

#define BB 8
#define CC 256
#define NN 4096      // H*W
#define GG 32
#define CPG 8
#define EPSV 1e-5f

// GEMM tiling (fp16 operands, fp32 accum)
#define BM 128
#define BN 256
#define BKH 32                         // K per stage, in half elements
#define PADH 8
#define ROWH (BKH + PADH)              // 40 half = 80 B = 20 words per row
#define A_STG_H (BM * ROWH)            // 5120 half
#define B_STG_H (BN * ROWH)            // 10240 half
#define STG_H (A_STG_H + B_STG_H)      // 15360 half = 30720 B
#define SMEM_BYTES (2 * STG_H * 2)     // 61440 B

// ---------------- scratch (device globals) -----------------------------------
__device__ float  g_mean[BB * GG];
__device__ float  g_rstd[BB * GG];
__device__ __half g_qT   [(size_t)BB * NN * CC];   // Q^T  [b][n][c], scaled
__device__ __half g_normT[(size_t)BB * NN * CC];   // GN(x)^T [b][n][c]
__device__ __half g_keyT [(size_t)BB * NN * CC];   // K^T  [b][n][c]
__device__ __half g_val  [(size_t)BB * CC * NN];   // V    [b][c][n]
__device__ __half g_attn [(size_t)BB * NN * NN];   // S/P  [b][m][n]  256 MB
__device__ __half g_aoT  [(size_t)BB * NN * CC];   // AO^T [b][n][c]
__device__ __half g_wkv_h[2 * CC * CC];
__device__ __half g_wout_h[CC * CC];

// ---------------- 1. GroupNorm statistics ------------------------------------
__global__ void gn_stats(const float* __restrict__ x) {
    const int bg = blockIdx.x;
    const float* p = x + (size_t)bg * (CPG * NN);
    const int tid = threadIdx.x;
    float s = 0.f, s2 = 0.f;
    for (int i = tid; i < CPG * NN; i += 256) {
        float v = p[i];
        s += v; s2 += v * v;
    }
    __shared__ float sh[256], sh2[256];
    sh[tid] = s; sh2[tid] = s2;
    __syncthreads();
    for (int o = 128; o > 0; o >>= 1) {
        if (tid < o) { sh[tid] += sh[tid + o]; sh2[tid] += sh2[tid + o]; }
        __syncthreads();
    }
    if (tid == 0) {
        const float inv_n = 1.f / (CPG * NN);
        float m   = sh[0] * inv_n;
        float var = sh2[0] * inv_n - m * m;
        g_mean[bg] = m;
        g_rstd[bg] = rsqrtf(var + EPSV);
    }
}

// ---------------- 2. weights -> fp16 -----------------------------------------
__global__ void round_w(const float* __restrict__ wkv,
                        const float* __restrict__ wout) {
    int i = blockIdx.x * 256 + threadIdx.x;
    if (i < 2 * CC * CC) g_wkv_h[i] = __float2half_rn(wkv[i]);
    if (i < CC * CC)     g_wout_h[i] = __float2half_rn(wout[i]);
}

// ---------------- 3. Q projection, transposed + scaled -> fp16 ---------------
__global__ void q_proj_t(const float* __restrict__ qin,   // [B,3,N]
                         const float* __restrict__ wq) {  // [C,3]
    size_t idx = (size_t)blockIdx.x * 256 + threadIdx.x;
    if (idx >= (size_t)BB * NN * CC) return;
    int c = (int)(idx & (CC - 1));
    int n = (int)((idx >> 8) & (NN - 1));
    int b = (int)(idx >> 20);
    const float* qb = qin + (size_t)b * 3 * NN + n;
    g_qT[idx] = __float2half_rn(0.0625f * (wq[c * 3 + 0] * qb[0]
                                         + wq[c * 3 + 1] * qb[NN]
                                         + wq[c * 3 + 2] * qb[2 * NN]));
}

// ---------------- 4. GroupNorm apply + transpose -> fp16 ---------------------
__global__ void __launch_bounds__(256) norm_t(const float* __restrict__ x,
                                              const float* __restrict__ gamma,
                                              const float* __restrict__ beta) {
    __shared__ float t[32][33];
    const int b  = blockIdx.z;
    const int n0 = blockIdx.x * 32, c0 = blockIdx.y * 32;
    const int tx = threadIdx.x, ty = threadIdx.y;
#pragma unroll
    for (int i = 0; i < 4; i++) {
        int c  = c0 + ty + i * 8;
        int bg = b * GG + (c >> 3);
        float sc = g_rstd[bg] * gamma[c];
        float sh = beta[c] - g_mean[bg] * sc;
        float v = x[((size_t)b * CC + c) * NN + n0 + tx];
        t[ty + i * 8][tx] = v * sc + sh;
    }
    __syncthreads();
#pragma unroll
    for (int i = 0; i < 4; i++) {
        int n = n0 + ty + i * 8;
        g_normT[((size_t)b * NN + n) * CC + c0 + tx] =
            __float2half_rn(t[tx][ty + i * 8]);
    }
}

// ---------------- generic TN fp16 tensor-core GEMM (cp.async pipelined) ------
// C[m][n] = sum_k A[m][k] * B[n][k]; A,B fp16 k-contiguous.
// mode 0: fp32 out [m][n] + optional bias[m] + resid
// mode 1: fp16 out [m][n]
// mode 2: KV split — m < CC -> keyT[n][m] fp16, m >= CC -> val[m-CC][n] fp16
#define CP16(d, s) asm volatile("cp.async.cg.shared.global [%0], [%1], 16;" :: "r"(d), "l"(s))

__global__ void __launch_bounds__(256) gemm_tn_f16(
    const __half* __restrict__ Ag, const __half* __restrict__ Bg,
    void* __restrict__ Cg, __half* __restrict__ Ct,
    const float* __restrict__ bias, const float* __restrict__ resid,
    int K, int ldc, int ldct, int mode,
    size_t sA, size_t sB, size_t sC, size_t sCt, size_t sR)
{
    extern __shared__ __half sm[];
    const int b = blockIdx.z;
    const __half* A = Ag + (size_t)b * sA;
    const __half* B = Bg + (size_t)b * sB;
    const int m0 = blockIdx.y * BM;
    const int n0 = blockIdx.x * BN;

    const int tid  = threadIdx.x;
    const int lane = tid & 31;
    const int warp = tid >> 5;
    const int wm = (warp & 1) * 64;
    const int wn = (warp >> 1) * 64;
    const int g = lane >> 2, t = lane & 3;

    // cp.async mapping: 4 threads/row, 16B (8 half) each
    const int r4 = tid >> 2;           // 0..63
    const int c8 = (tid & 3) * 8;      // half offset within row: 0,8,16,24
    const __half* Ap = A + (size_t)(m0 + r4) * K + c8;
    const __half* Bp = B + (size_t)(n0 + r4) * K + c8;
    const uint32_t sbase = (uint32_t)__cvta_generic_to_shared(sm);

#define ISSUE(s, ko)                                                          \
    do {                                                                      \
        uint32_t as_ = sbase + (uint32_t)(s) * (STG_H * 2);                   \
        uint32_t bs_ = as_ + A_STG_H * 2;                                     \
        const __half* ap_ = Ap + (ko);                                        \
        const __half* bp_ = Bp + (ko);                                        \
        CP16(as_ + (r4 * ROWH + c8) * 2,         ap_);                        \
        CP16(as_ + ((r4 + 64) * ROWH + c8) * 2,  ap_ + (size_t)64 * K);       \
        CP16(bs_ + (r4 * ROWH + c8) * 2,         bp_);                        \
        CP16(bs_ + ((r4 + 64) * ROWH + c8) * 2,  bp_ + (size_t)64 * K);       \
        CP16(bs_ + ((r4 + 128) * ROWH + c8) * 2, bp_ + (size_t)128 * K);      \
        CP16(bs_ + ((r4 + 192) * ROWH + c8) * 2, bp_ + (size_t)192 * K);      \
        asm volatile("cp.async.commit_group;");                               \
    } while (0)

    float acc[4][8][4];
#pragma unroll
    for (int mi = 0; mi < 4; mi++)
#pragma unroll
        for (int ni = 0; ni < 8; ni++)
#pragma unroll
            for (int r = 0; r < 4; r++) acc[mi][ni][r] = 0.f;

    const int iters = K / BKH;
    ISSUE(0, 0);
    ISSUE(1, BKH);
    asm volatile("cp.async.wait_group 1;");
    __syncthreads();

    for (int it = 0; it < iters; ++it) {
        const uint32_t* As = (const uint32_t*)(sm + (it & 1) * STG_H);
        const uint32_t* Bs = As + (A_STG_H >> 1);

#pragma unroll
        for (int kk = 0; kk < 2; kk++) {            // two k16 steps
            uint32_t af[4][4], bf[8][2];
#pragma unroll
            for (int mi = 0; mi < 4; mi++) {
                const uint32_t* p = As + (wm + mi * 16 + g) * (ROWH / 2) + kk * 8 + t;
                af[mi][0] = p[0];
                af[mi][1] = p[8 * (ROWH / 2)];
                af[mi][2] = p[4];
                af[mi][3] = p[8 * (ROWH / 2) + 4];
            }
#pragma unroll
            for (int ni = 0; ni < 8; ni++) {
                const uint32_t* p = Bs + (wn + ni * 8 + g) * (ROWH / 2) + kk * 8 + t;
                bf[ni][0] = p[0];
                bf[ni][1] = p[4];
            }
#pragma unroll
            for (int mi = 0; mi < 4; mi++)
#pragma unroll
                for (int ni = 0; ni < 8; ni++) {
                    float* d = acc[mi][ni];
                    asm volatile(
                        "mma.sync.aligned.m16n8k16.row.col.f32.f16.f16.f32 "
                        "{%0,%1,%2,%3}, {%4,%5,%6,%7}, {%8,%9}, {%0,%1,%2,%3};"
                        : "+f"(d[0]), "+f"(d[1]), "+f"(d[2]), "+f"(d[3])
                        : "r"(af[mi][0]), "r"(af[mi][1]), "r"(af[mi][2]), "r"(af[mi][3]),
                          "r"(bf[ni][0]), "r"(bf[ni][1]));
                }
        }
        __syncthreads();
        if (it + 2 < iters) {
            ISSUE(it & 1, (size_t)(it + 2) * BKH);
            asm volatile("cp.async.wait_group 1;");
        } else {
            asm volatile("cp.async.wait_group 0;");
        }
        __syncthreads();
    }

    // ---------------- epilogue ----------------
    if (mode == 0) {
        float* Cb = (float*)Cg + (size_t)b * sC;
#pragma unroll
        for (int mi = 0; mi < 4; mi++)
#pragma unroll
            for (int ni = 0; ni < 8; ni++) {
                int row = m0 + wm + mi * 16 + g;
                int col = n0 + wn + ni * 8 + t * 2;
                float* d = acc[mi][ni];
                float2 v0 = make_float2(d[0], d[1]);
                float2 v1 = make_float2(d[2], d[3]);
                if (bias) {
                    float b0 = bias[row], b1 = bias[row + 8];
                    v0.x += b0; v0.y += b0;
                    v1.x += b1; v1.y += b1;
                }
                if (resid) {
                    const float* R = resid + (size_t)b * sR;
                    float2 r0 = *(const float2*)&R[(size_t)row * ldc + col];
                    float2 r1 = *(const float2*)&R[(size_t)(row + 8) * ldc + col];
                    v0.x += r0.x; v0.y += r0.y;
                    v1.x += r1.x; v1.y += r1.y;
                }
                *(float2*)&Cb[(size_t)row * ldc + col]       = v0;
                *(float2*)&Cb[(size_t)(row + 8) * ldc + col] = v1;
            }
    } else if (mode == 1) {
        __half* Cb = (__half*)Cg + (size_t)b * sC;
#pragma unroll
        for (int mi = 0; mi < 4; mi++)
#pragma unroll
            for (int ni = 0; ni < 8; ni++) {
                int row = m0 + wm + mi * 16 + g;
                int col = n0 + wn + ni * 8 + t * 2;
                float* d = acc[mi][ni];
                *(__half2*)&Cb[(size_t)row * ldc + col] =
                    __floats2half2_rn(d[0], d[1]);
                *(__half2*)&Cb[(size_t)(row + 8) * ldc + col] =
                    __floats2half2_rn(d[2], d[3]);
            }
    } else {
        // KV split (branch uniform per block: m0 either < CC or >= CC)
        __half* Tb = Ct + (size_t)b * sCt;               // keyT [n][c]
        __half* Vb = (__half*)Cg + (size_t)b * sC;       // val  [c][n]
#pragma unroll
        for (int mi = 0; mi < 4; mi++)
#pragma unroll
            for (int ni = 0; ni < 8; ni++) {
                int row = m0 + wm + mi * 16 + g;
                int col = n0 + wn + ni * 8 + t * 2;
                float* d = acc[mi][ni];
                if (row < CC) {
                    Tb[(size_t)col * ldct + row]           = __float2half_rn(d[0]);
                    Tb[(size_t)(col + 1) * ldct + row]     = __float2half_rn(d[1]);
                    Tb[(size_t)col * ldct + row + 8]       = __float2half_rn(d[2]);
                    Tb[(size_t)(col + 1) * ldct + row + 8] = __float2half_rn(d[3]);
                } else {
                    *(__half2*)&Vb[(size_t)(row - CC) * ldc + col] =
                        __floats2half2_rn(d[0], d[1]);
                    *(__half2*)&Vb[(size_t)(row - CC + 8) * ldc + col] =
                        __floats2half2_rn(d[2], d[3]);
                }
            }
    }
#undef ISSUE
}

// ---------------- row softmax (rows of 4096 fp16) ----------------------------
__global__ void __launch_bounds__(256) softmax_k() {
    const size_t row = blockIdx.x;
    uint4* p = (uint4*)(g_attn + row * NN);   // 512 uint4 per row
    const int tid = threadIdx.x;
    const int lane = tid & 31, wid = tid >> 5;
    __shared__ float sh[8];

    uint4 raw[2];
    float v[16];
#pragma unroll
    for (int i = 0; i < 2; i++) raw[i] = p[tid + i * 256];
#pragma unroll
    for (int i = 0; i < 2; i++) {
        const __half2* h = (const __half2*)&raw[i];
#pragma unroll
        for (int j = 0; j < 4; j++) {
            float2 f = __half22float2(h[j]);
            v[i * 8 + j * 2]     = f.x;
            v[i * 8 + j * 2 + 1] = f.y;
        }
    }
    float mx = v[0];
#pragma unroll
    for (int i = 1; i < 16; i++) mx = fmaxf(mx, v[i]);
#pragma unroll
    for (int o = 16; o > 0; o >>= 1)
        mx = fmaxf(mx, __shfl_xor_sync(0xffffffffu, mx, o));
    if (lane == 0) sh[wid] = mx;
    __syncthreads();
    mx = sh[0];
#pragma unroll
    for (int i = 1; i < 8; i++) mx = fmaxf(mx, sh[i]);

    float s = 0.f;
#pragma unroll
    for (int i = 0; i < 16; i++) {
        v[i] = __expf(v[i] - mx);
        s += v[i];
    }
#pragma unroll
    for (int o = 16; o > 0; o >>= 1)
        s += __shfl_xor_sync(0xffffffffu, s, o);
    __syncthreads();
    if (lane == 0) sh[wid] = s;
    __syncthreads();
    s = 0.f;
#pragma unroll
    for (int i = 0; i < 8; i++) s += sh[i];
    float inv = 1.f / s;

#pragma unroll
    for (int i = 0; i < 2; i++) {
        __half2* h = (__half2*)&raw[i];
#pragma unroll
        for (int j = 0; j < 4; j++)
            h[j] = __floats2half2_rn(v[i * 8 + j * 2] * inv,
                                     v[i * 8 + j * 2 + 1] * inv);
        p[tid + i * 256] = raw[i];
    }
}

// ---------------- launch ------------------------------------------------------
extern "C" void kernel_launch(void* const* d_in, const int* in_sizes, int n_in,
                              void* d_out, int out_size) {
    const float* input = (const float*)d_in[0];
    const float* quary = (const float*)d_in[1];
    const float* gw    = (const float*)d_in[2];
    const float* gb    = (const float*)d_in[3];
    const float* wq    = (const float*)d_in[4];
    const float* wkv   = (const float*)d_in[5];
    const float* wout  = (const float*)d_in[6];
    const float* bout  = (const float*)d_in[7];
    float* out = (float*)d_out;

    static int smem_set = 0;
    if (!smem_set) {
        cudaFuncSetAttribute(gemm_tn_f16,
                             cudaFuncAttributeMaxDynamicSharedMemorySize, SMEM_BYTES);
        smem_set = 1;
    }

    __half *p_qT, *p_normT, *p_keyT, *p_val, *p_attn, *p_aoT, *p_wkv, *p_wout;
    cudaGetSymbolAddress((void**)&p_qT,    g_qT);
    cudaGetSymbolAddress((void**)&p_normT, g_normT);
    cudaGetSymbolAddress((void**)&p_keyT,  g_keyT);
    cudaGetSymbolAddress((void**)&p_val,   g_val);
    cudaGetSymbolAddress((void**)&p_attn,  g_attn);
    cudaGetSymbolAddress((void**)&p_aoT,   g_aoT);
    cudaGetSymbolAddress((void**)&p_wkv,   g_wkv_h);
    cudaGetSymbolAddress((void**)&p_wout,  g_wout_h);

    const size_t sCN  = (size_t)CC * NN;
    const size_t sNC  = (size_t)NN * CC;
    const size_t sNNb = (size_t)NN * NN;

    gn_stats<<<BB * GG, 256>>>(input);
    round_w<<<512, 256>>>(wkv, wout);
    q_proj_t<<<(int)(((size_t)BB * NN * CC + 255) / 256), 256>>>(quary, wq);
    norm_t<<<dim3(NN / 32, CC / 32, BB), dim3(32, 8)>>>(input, gw, gb);

    // KV: A = wkv_h [512][256], B = normT -> keyT + val (split)
    gemm_tn_f16<<<dim3(NN / BN, 512 / BM, BB), 256, SMEM_BYTES>>>(
        p_wkv, p_normT, p_val, p_keyT, nullptr, nullptr,
        CC, NN, CC, 2, 0, sNC, sCN, sNC, 0);

    // S = Q^T K : A = qT, B = keyT -> attn fp16 [m][n]
    gemm_tn_f16<<<dim3(NN / BN, NN / BM, BB), 256, SMEM_BYTES>>>(
        p_qT, p_keyT, p_attn, nullptr, nullptr, nullptr,
        CC, NN, 0, 1, sNC, sNC, sNNb, 0, 0);

    softmax_k<<<BB * NN, 256>>>();

    // AO^T: A = P [q][j], B = val [c][j] -> aoT fp16 [q][c]
    gemm_tn_f16<<<dim3(CC / BN, NN / BM, BB), 256, SMEM_BYTES>>>(
        p_attn, p_val, p_aoT, nullptr, nullptr, nullptr,
        NN, CC, 0, 1, sNNb, sCN, sNC, 0, 0);

    // out = W_out AO + b + input (fp32)
    gemm_tn_f16<<<dim3(NN / BN, CC / BM, BB), 256, SMEM_BYTES>>>(
        p_wout, p_aoT, out, nullptr, bout, input,
        CC, NN, 0, 0, 0, sNC, sCN, 0, sCN);
}